// round 14
// baseline (speedup 1.0000x reference)
#include <cuda_runtime.h>
#include <math.h>

#define N_B   1024
#define N_S   4096
#define N_G   60
#define EMB   64

// ---------------- device scratch (allocation-free rule: globals only) -------
__device__ float  g_hyp_s[N_S * EMB];
__device__ float  g_hyp_g[N_G * EMB];
__device__ float  g_ys2[N_S];     // ||hyp_s||^2
__device__ float  g_yg2[N_G];     // ||hyp_g||^2
__device__ float  g_x2[N_B];      // ||X_b||^2
__device__ int    g_present[N_S]; // zero-init at load; idempotent stores of 1
__device__ int    g_validg[N_G];  // same
__device__ double g_acc[4];       // S1 (sp pos), S2 (sp neg), S3 (g pos), S4 (g neg)

__device__ __forceinline__ float warpsum(float v) {
#pragma unroll
    for (int o = 16; o; o >>= 1) v += __shfl_xor_sync(0xffffffffu, v, o);
    return v;
}

// ---------------------------------------------------------------------------
// dist + softplus fusion.
//   a = -x, m = a.y = -(x.y)
//   coef_a = 1 + 2c m + c y2 ; coef_y = 1 - c a2
//   num2   = coef_a^2 a2 + 2 coef_a coef_y m + coef_y^2 y2
//   denom  = 1 + 2c m + c^2 a2 y2
//   t      = clip( sqrt(c*num2)/max(|denom|,1e-15), 0, 1-1e-5 )
//   d      = (2/sc) atanh(t) = ln((1+t)/(1-t))/sc
//   softplus(-d) = ln(1 + e^{-d}) ; softplus(d) = d + softplus(-d)
// ---------------------------------------------------------------------------
__device__ __forceinline__ void pair_acc(float dotxy, float a2, float y2,
                                         bool matched, float& Spos, float& Sneg)
{
    const float Cc = 0.1f;
    float m      = -dotxy;
    float coef_a = 1.0f + 0.2f * m + Cc * y2;
    float coef_y = 1.0f - Cc * a2;
    float num2   = (coef_a * coef_a) * a2
                 + (2.0f * coef_a * coef_y) * m
                 + (coef_y * coef_y) * y2;
    float denom  = 1.0f + 0.2f * m + 0.01f * (a2 * y2);
    float dd     = fmaxf(fabsf(denom), 1e-15f);
    float n      = sqrtf(fmaxf(num2, 0.0f) * Cc);       // = sc * ||num||
    n            = fminf(n, (1.0f - 1e-5f) * dd);       // arg clip
    float u      = __fdividef(dd + n, dd - n);          // (1+t)/(1-t)
    float Lu     = __log2f(u);
    float d      = Lu * 2.1919238f;                     // ln2 / sqrt(0.1)
    float spn    = __logf(1.0f + __expf(-d));           // softplus(-d), d >= 0
    if (matched) Spos += d + spn;
    else         Sneg += spn;
}

// ---------------------------------------------------------------------------
// k_prep: warp per row.
//   rows [0, 4096)            : project species proxies -> g_hyp_s, g_ys2
//   rows [4096, 4156)         : project genus proxies   -> g_hyp_g, g_yg2
//   rows [4156, 5180)         : ||X_b||^2 + present scatter
// Also zeroes the 4 accumulators (block 0).
// ---------------------------------------------------------------------------
__global__ void k_prep(const float* __restrict__ X, const int* __restrict__ Tsp,
                       const float* __restrict__ gtan, const float* __restrict__ stan)
{
    if (blockIdx.x == 0 && threadIdx.x < 4) g_acc[threadIdx.x] = 0.0;

    int warpId = threadIdx.x >> 5;
    int lane   = threadIdx.x & 31;
    int row    = blockIdx.x * 4 + warpId;

    const float SC = 0.31622776601683794f;   // sqrt(0.1)

    if (row < N_S + N_G) {
        const float* src; float* dst; float* n2dst;
        if (row < N_S) { src = stan + row * EMB;         dst = g_hyp_s + row * EMB;         n2dst = g_ys2 + row; }
        else           { int r = row - N_S;
                         src = gtan + r * EMB;           dst = g_hyp_g + r * EMB;           n2dst = g_yg2 + r; }
        float a0 = src[lane], a1 = src[lane + 32];
        float nrm = fmaxf(sqrtf(warpsum(a0 * a0 + a1 * a1)), 1e-5f);
        float s1  = fminf(1.0f, 2.3f / nrm);
        a0 *= s1; a1 *= s1;
        float n2  = fmaxf(sqrtf(warpsum(a0 * a0 + a1 * a1)), 1e-5f);
        float scn = SC * n2;
        float f   = tanhf(scn) / scn;
        float y0 = f * a0, y1 = f * a1;
        float yn  = fmaxf(sqrtf(warpsum(y0 * y0 + y1 * y1)), 1e-5f);
        float maxn = (float)(0.999 / 0.31622776601683794);   // (1-1e-3)/sqrt_c
        if (yn > maxn) { float rr = maxn / yn; y0 *= rr; y1 *= rr; }
        dst[lane] = y0; dst[lane + 32] = y1;
        float fn2 = warpsum(y0 * y0 + y1 * y1);
        if (lane == 0) *n2dst = fn2;
    } else {
        int b = row - (N_S + N_G);
        if (b < N_B) {
            float a0 = X[b * EMB + lane], a1 = X[b * EMB + lane + 32];
            float s = warpsum(a0 * a0 + a1 * a1);
            if (lane == 0) { g_x2[b] = s; g_present[Tsp[b]] = 1; }
        }
    }
}

// ---------------------------------------------------------------------------
// k_main: blocks [0,1024) -> species loss tiles (64 b x 64 s, 4x4/thread)
//         blocks [1024,1088) -> genus loss tiles (64 s x 60 g)
// ---------------------------------------------------------------------------
__global__ __launch_bounds__(256) void k_main(const float* __restrict__ X,
                                              const int* __restrict__ Tsp,
                                              const int* __restrict__ s2g)
{
    __shared__ float shA[64 * 65];
    __shared__ float shB[64 * 65];
    __shared__ float shA2[64];
    __shared__ float shB2[64];
    __shared__ int   shTi[64];
    __shared__ int   shPr[64];
    __shared__ float red[16];

    int tid = threadIdx.x;

    if (blockIdx.x < 1024) {
        // ----------------- species proxy-anchor tile ------------------------
        int bx = blockIdx.x & 63, by = blockIdx.x >> 6;
        int b0 = by * 64, s0 = bx * 64;
#pragma unroll
        for (int i = 0; i < 16; i++) {
            int idx = tid + i * 256;
            int r = idx >> 6, c = idx & 63;
            shA[r * 65 + c] = X[(b0 + r) * EMB + c];
            shB[r * 65 + c] = g_hyp_s[(s0 + r) * EMB + c];
        }
        if (tid < 64)       { shA2[tid] = g_x2[b0 + tid]; shTi[tid] = Tsp[b0 + tid]; }
        else if (tid < 128) { int t = tid - 64; shB2[t] = g_ys2[s0 + t]; }
        __syncthreads();

        int ty = tid >> 4, tx = tid & 15;
        float acc[4][4];
#pragma unroll
        for (int i = 0; i < 4; i++)
#pragma unroll
            for (int j = 0; j < 4; j++) acc[i][j] = 0.0f;

        const float* ap = &shA[(ty * 4) * 65];
        const float* bp = &shB[(tx * 4) * 65];
#pragma unroll 16
        for (int k = 0; k < 64; k++) {
            float xa[4], xb[4];
#pragma unroll
            for (int i = 0; i < 4; i++) xa[i] = ap[i * 65 + k];
#pragma unroll
            for (int j = 0; j < 4; j++) xb[j] = bp[j * 65 + k];
#pragma unroll
            for (int i = 0; i < 4; i++)
#pragma unroll
                for (int j = 0; j < 4; j++)
                    acc[i][j] = fmaf(xa[i], xb[j], acc[i][j]);
        }

        float S1 = 0.0f, S2 = 0.0f;
#pragma unroll
        for (int i = 0; i < 4; i++) {
            int bl = ty * 4 + i;
            float a2 = shA2[bl];
            int tspec = shTi[bl];
#pragma unroll
            for (int j = 0; j < 4; j++) {
                int sl = tx * 4 + j;
                pair_acc(acc[i][j], a2, shB2[sl], tspec == (s0 + sl), S1, S2);
            }
        }
        S1 = warpsum(S1); S2 = warpsum(S2);
        int w = tid >> 5, ln = tid & 31;
        if (ln == 0) { red[w] = S1; red[w + 8] = S2; }
        __syncthreads();
        if (tid == 0) {
            float a = 0.0f, b = 0.0f;
            for (int q = 0; q < 8; q++) { a += red[q]; b += red[q + 8]; }
            atomicAdd(&g_acc[0], (double)a);
            atomicAdd(&g_acc[1], (double)b);
        }
    } else {
        // ----------------- genus proxy-anchor tile --------------------------
        int blk = blockIdx.x - 1024;          // 0..63
        int s0 = blk * 64;
#pragma unroll
        for (int i = 0; i < 16; i++) {
            int idx = tid + i * 256;
            int r = idx >> 6, c = idx & 63;
            shA[r * 65 + c] = g_hyp_s[(s0 + r) * EMB + c];
            if (idx < N_G * EMB) shB[r * 65 + c] = g_hyp_g[idx];
        }
        if (tid < 64) { shA2[tid] = g_ys2[s0 + tid]; shTi[tid] = s2g[s0 + tid]; shPr[tid] = g_present[s0 + tid]; }
        else if (tid < 124) { shB2[tid - 64] = g_yg2[tid - 64]; }
        __syncthreads();

        int sl = tid >> 2, q = tid & 3;       // 64 species x 4 genus-groups(15)
        float a2 = shA2[sl];
        int   sg = shTi[sl];
        int   pr = shPr[sl];
        if (q == 0 && pr) g_validg[sg] = 1;

        float acc[15];
#pragma unroll
        for (int j = 0; j < 15; j++) acc[j] = 0.0f;
        const float* ap = &shA[sl * 65];
        const float* gp = &shB[(q * 15) * 65];
#pragma unroll 8
        for (int k = 0; k < 64; k++) {
            float xv = ap[k];
#pragma unroll
            for (int j = 0; j < 15; j++)
                acc[j] = fmaf(xv, gp[j * 65 + k], acc[j]);
        }

        float S3 = 0.0f, S4 = 0.0f;
        if (pr) {
#pragma unroll
            for (int j = 0; j < 15; j++) {
                int g = q * 15 + j;
                pair_acc(acc[j], a2, shB2[g], sg == g, S3, S4);
            }
        }
        S3 = warpsum(S3); S4 = warpsum(S4);
        int w = tid >> 5, ln = tid & 31;
        if (ln == 0) { red[w] = S3; red[w + 8] = S4; }
        __syncthreads();
        if (tid == 0) {
            float a = 0.0f, b = 0.0f;
            for (int q2 = 0; q2 < 8; q2++) { a += red[q2]; b += red[q2 + 8]; }
            atomicAdd(&g_acc[2], (double)a);
            atomicAdd(&g_acc[3], (double)b);
        }
    }
}

// ---------------------------------------------------------------------------
// k_final: nvs = sum(present), nvg = sum(validg), combine partial sums.
// ---------------------------------------------------------------------------
__global__ void k_final(float* __restrict__ out)
{
    __shared__ int sred[256];
    int tid = threadIdx.x;

    int cnt = 0;
    for (int s = tid; s < N_S; s += 256) cnt += g_present[s];
    sred[tid] = cnt;
    __syncthreads();
    for (int o = 128; o; o >>= 1) { if (tid < o) sred[tid] += sred[tid + o]; __syncthreads(); }
    int nvs = sred[0];
    __syncthreads();

    sred[tid] = (tid < N_G) ? g_validg[tid] : 0;
    __syncthreads();
    for (int o = 128; o; o >>= 1) { if (tid < o) sred[tid] += sred[tid + o]; __syncthreads(); }

    if (tid == 0) {
        int nvg = sred[0];
        double loss = g_acc[0] / fmax((double)nvs, 1.0)
                    + g_acc[1] / (double)N_S
                    + g_acc[2] / fmax((double)nvg, 1.0)
                    + g_acc[3] / (double)N_G;
        out[0] = (float)loss;
    }
}

// ---------------------------------------------------------------------------
extern "C" void kernel_launch(void* const* d_in, const int* in_sizes, int n_in,
                              void* d_out, int out_size)
{
    (void)in_sizes; (void)n_in; (void)out_size;
    const float* X    = (const float*)d_in[0];
    const int*   Tsp  = (const int*)  d_in[1];
    // d_in[2] = T_genus (unused by the loss)
    const int*   s2g  = (const int*)  d_in[3];
    const float* gtan = (const float*)d_in[4];
    const float* stan = (const float*)d_in[5];

    // 4096 + 60 + 1024 = 5180 warp-rows, 4 warps/block -> 1295 blocks
    k_prep<<<1295, 128>>>(X, Tsp, gtan, stan);
    // 1024 species tiles + 64 genus tiles
    k_main<<<1024 + 64, 256>>>(X, Tsp, s2g);
    k_final<<<1, 256>>>((float*)d_out);
}

// round 15
// speedup vs baseline: 1.0368x; 1.0368x over previous
#include <cuda_runtime.h>
#include <math.h>

#define N_B   1024
#define N_S   4096
#define N_G   60
#define EMB   64

// ---------------- device scratch (allocation-free rule: globals only) -------
__device__ float  g_hyp_s[N_S * EMB];
__device__ float  g_hyp_g[N_G * EMB];
__device__ float  g_ys2[N_S];     // ||hyp_s||^2
__device__ float  g_yg2[N_G];     // ||hyp_g||^2
__device__ float  g_x2[N_B];      // ||X_b||^2
__device__ int    g_present[N_S]; // zero-init at load; idempotent stores of 1
__device__ int    g_validg[N_G];  // same
__device__ double g_acc[4];       // S1 (sp pos), S2 (sp neg), S3 (g pos), S4 (g neg)

__device__ __forceinline__ float warpsum(float v) {
#pragma unroll
    for (int o = 16; o; o >>= 1) v += __shfl_xor_sync(0xffffffffu, v, o);
    return v;
}

// ---------------------------------------------------------------------------
// dist + softplus fusion.
//   a = -x, m = a.y = -(x.y)
//   coef_a = 1 + 2c m + c y2 ; coef_y = 1 - c a2
//   num2   = coef_a^2 a2 + 2 coef_a coef_y m + coef_y^2 y2
//   denom  = 1 + 2c m + c^2 a2 y2
//   t      = clip( sqrt(c*num2)/max(|denom|,1e-15), 0, 1-1e-5 )
//   d      = (2/sc) atanh(t) = ln((1+t)/(1-t))/sc
//   softplus(-d) = ln(1 + e^{-d}) ; softplus(d) = d + softplus(-d)
// ---------------------------------------------------------------------------
__device__ __forceinline__ void pair_acc(float dotxy, float a2, float y2,
                                         bool matched, float& Spos, float& Sneg)
{
    const float Cc = 0.1f;
    float m      = -dotxy;
    float coef_a = 1.0f + 0.2f * m + Cc * y2;
    float coef_y = 1.0f - Cc * a2;
    float num2   = (coef_a * coef_a) * a2
                 + (2.0f * coef_a * coef_y) * m
                 + (coef_y * coef_y) * y2;
    float denom  = 1.0f + 0.2f * m + 0.01f * (a2 * y2);
    float dd     = fmaxf(fabsf(denom), 1e-15f);
    float n      = sqrtf(fmaxf(num2, 0.0f) * Cc);       // = sc * ||num||
    n            = fminf(n, (1.0f - 1e-5f) * dd);       // arg clip
    float u      = __fdividef(dd + n, dd - n);          // (1+t)/(1-t)
    float Lu     = __log2f(u);
    float d      = Lu * 2.1919238f;                     // ln2 / sqrt(0.1)
    float spn    = __logf(1.0f + __expf(-d));           // softplus(-d), d >= 0
    if (matched) Spos += d + spn;
    else         Sneg += spn;
}

// ---------------------------------------------------------------------------
// k_prep: warp per row.
//   rows [0, 4096)            : project species proxies -> g_hyp_s, g_ys2
//   rows [4096, 4156)         : project genus proxies   -> g_hyp_g, g_yg2
//   rows [4156, 5180)         : ||X_b||^2 + present scatter
// Also zeroes the 4 accumulators (block 0).
// ---------------------------------------------------------------------------
__global__ void k_prep(const float* __restrict__ X, const int* __restrict__ Tsp,
                       const float* __restrict__ gtan, const float* __restrict__ stan)
{
    if (blockIdx.x == 0 && threadIdx.x < 4) g_acc[threadIdx.x] = 0.0;

    int warpId = threadIdx.x >> 5;
    int lane   = threadIdx.x & 31;
    int row    = blockIdx.x * 4 + warpId;

    const float SC = 0.31622776601683794f;   // sqrt(0.1)

    if (row < N_S + N_G) {
        const float* src; float* dst; float* n2dst;
        if (row < N_S) { src = stan + row * EMB;         dst = g_hyp_s + row * EMB;         n2dst = g_ys2 + row; }
        else           { int r = row - N_S;
                         src = gtan + r * EMB;           dst = g_hyp_g + r * EMB;           n2dst = g_yg2 + r; }
        float a0 = src[lane], a1 = src[lane + 32];
        float nrm = fmaxf(sqrtf(warpsum(a0 * a0 + a1 * a1)), 1e-5f);
        float s1  = fminf(1.0f, 2.3f / nrm);
        a0 *= s1; a1 *= s1;
        float n2  = fmaxf(sqrtf(warpsum(a0 * a0 + a1 * a1)), 1e-5f);
        float scn = SC * n2;
        float f   = tanhf(scn) / scn;
        float y0 = f * a0, y1 = f * a1;
        float yn  = fmaxf(sqrtf(warpsum(y0 * y0 + y1 * y1)), 1e-5f);
        float maxn = (float)(0.999 / 0.31622776601683794);   // (1-1e-3)/sqrt_c
        if (yn > maxn) { float rr = maxn / yn; y0 *= rr; y1 *= rr; }
        dst[lane] = y0; dst[lane + 32] = y1;
        float fn2 = warpsum(y0 * y0 + y1 * y1);
        if (lane == 0) *n2dst = fn2;
    } else {
        int b = row - (N_S + N_G);
        if (b < N_B) {
            float a0 = X[b * EMB + lane], a1 = X[b * EMB + lane + 32];
            float s = warpsum(a0 * a0 + a1 * a1);
            if (lane == 0) { g_x2[b] = s; g_present[Tsp[b]] = 1; }
        }
    }
}

// ---------------------------------------------------------------------------
// k_main: blocks [0,1024) -> species loss tiles (64 b x 64 s, 4x4/thread)
//         blocks [1024,1088) -> genus loss tiles (64 s x 60 g)
// ---------------------------------------------------------------------------
__global__ __launch_bounds__(256) void k_main(const float* __restrict__ X,
                                              const int* __restrict__ Tsp,
                                              const int* __restrict__ s2g)
{
    __shared__ float shA[64 * 65];
    __shared__ float shB[64 * 65];
    __shared__ float shA2[64];
    __shared__ float shB2[64];
    __shared__ int   shTi[64];
    __shared__ int   shPr[64];
    __shared__ float red[16];

    int tid = threadIdx.x;

    if (blockIdx.x < 1024) {
        // ----------------- species proxy-anchor tile ------------------------
        int bx = blockIdx.x & 63, by = blockIdx.x >> 6;
        int b0 = by * 64, s0 = bx * 64;
#pragma unroll
        for (int i = 0; i < 16; i++) {
            int idx = tid + i * 256;
            int r = idx >> 6, c = idx & 63;
            shA[r * 65 + c] = X[(b0 + r) * EMB + c];
            shB[r * 65 + c] = g_hyp_s[(s0 + r) * EMB + c];
        }
        if (tid < 64)       { shA2[tid] = g_x2[b0 + tid]; shTi[tid] = Tsp[b0 + tid]; }
        else if (tid < 128) { int t = tid - 64; shB2[t] = g_ys2[s0 + t]; }
        __syncthreads();

        int ty = tid >> 4, tx = tid & 15;
        float acc[4][4];
#pragma unroll
        for (int i = 0; i < 4; i++)
#pragma unroll
            for (int j = 0; j < 4; j++) acc[i][j] = 0.0f;

        const float* ap = &shA[(ty * 4) * 65];
        const float* bp = &shB[(tx * 4) * 65];
#pragma unroll 16
        for (int k = 0; k < 64; k++) {
            float xa[4], xb[4];
#pragma unroll
            for (int i = 0; i < 4; i++) xa[i] = ap[i * 65 + k];
#pragma unroll
            for (int j = 0; j < 4; j++) xb[j] = bp[j * 65 + k];
#pragma unroll
            for (int i = 0; i < 4; i++)
#pragma unroll
                for (int j = 0; j < 4; j++)
                    acc[i][j] = fmaf(xa[i], xb[j], acc[i][j]);
        }

        float S1 = 0.0f, S2 = 0.0f;
#pragma unroll
        for (int i = 0; i < 4; i++) {
            int bl = ty * 4 + i;
            float a2 = shA2[bl];
            int tspec = shTi[bl];
#pragma unroll
            for (int j = 0; j < 4; j++) {
                int sl = tx * 4 + j;
                pair_acc(acc[i][j], a2, shB2[sl], tspec == (s0 + sl), S1, S2);
            }
        }
        S1 = warpsum(S1); S2 = warpsum(S2);
        int w = tid >> 5, ln = tid & 31;
        if (ln == 0) { red[w] = S1; red[w + 8] = S2; }
        __syncthreads();
        if (tid == 0) {
            float a = 0.0f, b = 0.0f;
            for (int q = 0; q < 8; q++) { a += red[q]; b += red[q + 8]; }
            atomicAdd(&g_acc[0], (double)a);
            atomicAdd(&g_acc[1], (double)b);
        }
    } else {
        // ----------------- genus proxy-anchor tile --------------------------
        int blk = blockIdx.x - 1024;          // 0..63
        int s0 = blk * 64;
#pragma unroll
        for (int i = 0; i < 16; i++) {
            int idx = tid + i * 256;
            int r = idx >> 6, c = idx & 63;
            shA[r * 65 + c] = g_hyp_s[(s0 + r) * EMB + c];
            if (idx < N_G * EMB) shB[r * 65 + c] = g_hyp_g[idx];
        }
        if (tid < 64) { shA2[tid] = g_ys2[s0 + tid]; shTi[tid] = s2g[s0 + tid]; shPr[tid] = g_present[s0 + tid]; }
        else if (tid < 124) { shB2[tid - 64] = g_yg2[tid - 64]; }
        __syncthreads();

        int sl = tid >> 2, q = tid & 3;       // 64 species x 4 genus-groups(15)
        float a2 = shA2[sl];
        int   sg = shTi[sl];
        int   pr = shPr[sl];
        if (q == 0 && pr) g_validg[sg] = 1;

        float acc[15];
#pragma unroll
        for (int j = 0; j < 15; j++) acc[j] = 0.0f;
        const float* ap = &shA[sl * 65];
        const float* gp = &shB[(q * 15) * 65];
#pragma unroll 8
        for (int k = 0; k < 64; k++) {
            float xv = ap[k];
#pragma unroll
            for (int j = 0; j < 15; j++)
                acc[j] = fmaf(xv, gp[j * 65 + k], acc[j]);
        }

        float S3 = 0.0f, S4 = 0.0f;
        if (pr) {
#pragma unroll
            for (int j = 0; j < 15; j++) {
                int g = q * 15 + j;
                pair_acc(acc[j], a2, shB2[g], sg == g, S3, S4);
            }
        }
        S3 = warpsum(S3); S4 = warpsum(S4);
        int w = tid >> 5, ln = tid & 31;
        if (ln == 0) { red[w] = S3; red[w + 8] = S4; }
        __syncthreads();
        if (tid == 0) {
            float a = 0.0f, b = 0.0f;
            for (int q2 = 0; q2 < 8; q2++) { a += red[q2]; b += red[q2 + 8]; }
            atomicAdd(&g_acc[2], (double)a);
            atomicAdd(&g_acc[3], (double)b);
        }
    }
}

// ---------------------------------------------------------------------------
// k_final: nvs = sum(present), nvg = sum(validg), combine partial sums.
// ---------------------------------------------------------------------------
__global__ void k_final(float* __restrict__ out)
{
    __shared__ int sred[256];
    int tid = threadIdx.x;

    int cnt = 0;
    for (int s = tid; s < N_S; s += 256) cnt += g_present[s];
    sred[tid] = cnt;
    __syncthreads();
    for (int o = 128; o; o >>= 1) { if (tid < o) sred[tid] += sred[tid + o]; __syncthreads(); }
    int nvs = sred[0];
    __syncthreads();

    sred[tid] = (tid < N_G) ? g_validg[tid] : 0;
    __syncthreads();
    for (int o = 128; o; o >>= 1) { if (tid < o) sred[tid] += sred[tid + o]; __syncthreads(); }

    if (tid == 0) {
        int nvg = sred[0];
        double loss = g_acc[0] / fmax((double)nvs, 1.0)
                    + g_acc[1] / (double)N_S
                    + g_acc[2] / fmax((double)nvg, 1.0)
                    + g_acc[3] / (double)N_G;
        out[0] = (float)loss;
    }
}

// ---------------------------------------------------------------------------
extern "C" void kernel_launch(void* const* d_in, const int* in_sizes, int n_in,
                              void* d_out, int out_size)
{
    (void)in_sizes; (void)n_in; (void)out_size;
    const float* X    = (const float*)d_in[0];
    const int*   Tsp  = (const int*)  d_in[1];
    // d_in[2] = T_genus (unused by the loss)
    const int*   s2g  = (const int*)  d_in[3];
    const float* gtan = (const float*)d_in[4];
    const float* stan = (const float*)d_in[5];

    // 4096 + 60 + 1024 = 5180 warp-rows, 4 warps/block -> 1295 blocks
    k_prep<<<1295, 128>>>(X, Tsp, gtan, stan);
    // 1024 species tiles + 64 genus tiles
    k_main<<<1024 + 64, 256>>>(X, Tsp, s2g);
    k_final<<<1, 256>>>((float*)d_out);
}